// round 10
// baseline (speedup 1.0000x reference)
#include <cuda_runtime.h>

#define LSEQ 512
#define BSZ 1024
#define NTAG 64
#define START_TAG 62
#define END_TAG 63

typedef unsigned long long ull;

// ---- packed f32x2 helpers (Blackwell FFMA2: only reachable via PTX) ----
__device__ __forceinline__ ull pack2(float lo, float hi) {
    ull d;
    asm("mov.b64 %0, {%1, %2};" : "=l"(d) : "f"(lo), "f"(hi));
    return d;
}
__device__ __forceinline__ void unpack2(ull v, float& lo, float& hi) {
    asm("mov.b64 {%0, %1}, %2;" : "=f"(lo), "=f"(hi) : "l"(v));
}
__device__ __forceinline__ ull fma2(ull a, ull b, ull c) {
    ull d;
    asm("fma.rn.f32x2 %0, %1, %2, %3;" : "=l"(d) : "l"(a), "l"(b), "l"(c));
    return d;
}
__device__ __forceinline__ ull add2(ull a, ull b) {
    ull d;
    asm("add.rn.f32x2 %0, %1, %2;" : "=l"(d) : "l"(a), "l"(b));
    return d;
}

// ============================================================================
// Fused CRF kernel, PAIR-PACKED BATCHES.
//
// One 64-thread block (2 warps) handles TWO batches (bA, bB). Thread owns
// tag t = tid for BOTH batches. v is stored in SMEM as float2 (vA[t],vB[t]):
// one LDS.128 carries 2 p-values x 2 batches, so 32 LDS.128 + 64 FFMA2 per
// thread-step serve two batch-steps. This halves the per-batch MIO return
// traffic (the measured invariant wall of rounds 1-9: 256B of v must reach
// each of 32 consumer lanes per batch-step = 64 MIO-cyc; two batches now
// share every wavefront). E is duplicated (e,e) so the f32x2 lanes carry
// (batch A, batch B):  acc2 += (E[t,p],E[t,p]) * (vA[p],vB[p]).
//
// Numerics identical to the proven R4 path, per batch: linear-domain
// v' = (E @ v) * exp(feat); renorm every 4 steps, deferred (per-warp
// butterfly max produced at l%4==3 into maxsh, consumed as 1/hi folded into
// exp(feat), c += log(hi), at the next l%4==0; maxsh preinit 1.0 so the
// first consume is a no-op; pending max at exit carries no obligation).
// Scales/c kept separate per batch (a shared scale risks underflow from
// inter-batch drift). feats/mask in a 2-deep register ring.
// Realpath (gold score) fused: warp w handles batch w's gold path.
// ============================================================================
__global__ void __launch_bounds__(64, 6) crf_fused_kernel(
    const float* __restrict__ feats,
    const int*   __restrict__ tags,
    const float* __restrict__ mask,
    const float* __restrict__ transition,
    float* __restrict__ out)
{
    __shared__ __align__(16) float2 vsh[2][NTAG];  // (vA[t], vB[t]) ping-pong
    __shared__ float maxshA[2], maxshB[2];         // per-warp butterfly maxes
    __shared__ float redA[2], redB[2];             // end-score partials
    __shared__ float redr[2], redl[2];             // realpath sums per batch

    const int tid  = threadIdx.x;
    const int w    = tid >> 5;
    const int lane = tid & 31;
    const int bA   = blockIdx.x * 2;
    const int bB   = bA + 1;
    const int t    = tid;            // tag owned by this thread (both batches)

    // Ed[p] = ( exp(T[t,p]), exp(T[t,p]) )  duplicated -- 64 ull = 128 regs
    ull Ed[NTAG];
#pragma unroll
    for (int p = 0; p < NTAG; ++p) {
        const float e = __expf(__ldg(transition + t * NTAG + p));
        Ed[p] = pack2(e, e);
    }

    // v0 = one-hot(START) for both batches; c = 0
    float vA = (t == START_TAG) ? 1.0f : 0.0f;
    float vB = vA;
    vsh[0][t] = make_float2(vA, vB);
    if (tid < 2) { maxshA[tid] = 1.0f; maxshB[tid] = 1.0f; }
    float cA = 0.0f, cB = 0.0f;

    // 2-deep register ring: feats for both batches + warp-uniform masks
    const float* fpA = feats + (size_t)bA * NTAG + t;
    const float* fpB = feats + (size_t)bB * NTAG + t;
    float frA[2], frB[2], mrA[2], mrB[2];
#pragma unroll
    for (int u = 0; u < 2; ++u) {
        frA[u] = __ldg(fpA + (size_t)u * (BSZ * NTAG));
        frB[u] = __ldg(fpB + (size_t)u * (BSZ * NTAG));
        mrA[u] = __ldg(mask + u * BSZ + bA);
        mrB[u] = __ldg(mask + u * BSZ + bB);
    }
    __syncthreads();

    for (int l4 = 0; l4 < LSEQ; l4 += 4) {
#pragma unroll
        for (int u = 0; u < 4; ++u) {
            const int l = l4 + u;
            const float fA = frA[l & 1], fB = frB[l & 1];
            const float mA = mrA[l & 1], mB = mrB[l & 1];
            int ln = l + 2;
            if (ln > LSEQ - 1) ln = LSEQ - 1;
            frA[l & 1] = __ldg(fpA + (size_t)ln * (BSZ * NTAG));
            frB[l & 1] = __ldg(fpB + (size_t)ln * (BSZ * NTAG));
            mrA[l & 1] = __ldg(mask + ln * BSZ + bA);
            mrB[l & 1] = __ldg(mask + ln * BSZ + bB);

            // consume deferred renorm (every 4th step), per batch
            float scaleA = 1.0f, scaleB = 1.0f;
            if (u == 0) {
                const float hiA = fmaxf(maxshA[0], maxshA[1]);
                const float hiB = fmaxf(maxshB[0], maxshB[1]);
                scaleA = __fdividef(1.0f, hiA);
                scaleB = __fdividef(1.0f, hiB);
                cA += __logf(hiA);
                cB += __logf(hiB);
            }
            const float efA = __expf(fA) * scaleA;   // off the MV chain
            const float efB = __expf(fB) * scaleB;

            // (v'A[t], v'B[t]) = sum_p (E[t,p],E[t,p]) * (vA[p],vB[p])
            // 4 independent f32x2 chains of depth 16; 32 LDS.128 total.
            const ulonglong2* vp = (const ulonglong2*)vsh[l & 1];
            ull a0 = 0ull, a1 = 0ull, a2 = 0ull, a3 = 0ull;
#pragma unroll
            for (int i = 0; i < 32; i += 2) {
                const ulonglong2 w0 = vp[i];       // pairs p=2i, 2i+1
                const ulonglong2 w1 = vp[i + 1];   // pairs p=2i+2, 2i+3
                a0 = fma2(Ed[2 * i],     w0.x, a0);
                a1 = fma2(Ed[2 * i + 1], w0.y, a1);
                a2 = fma2(Ed[2 * i + 2], w1.x, a2);
                a3 = fma2(Ed[2 * i + 3], w1.y, a3);
            }
            const ull s2 = add2(add2(a0, a2), add2(a1, a3));
            float sA, sB;
            unpack2(s2, sA, sB);
            float nA = sA * efA;
            float nB = sB * efB;

            // masked step keeps old v (pending scale still applies)
            if (mA == 0.0f) nA = vA * scaleA;
            if (mB == 0.0f) nB = vB * scaleB;
            vA = nA;
            vB = nB;
            vsh[(l & 1) ^ 1][t] = make_float2(nA, nB);   // STS.64

            if (u == 3) {   // produce next renorm factors (per warp)
                float hiA = nA, hiB = nB;
#pragma unroll
                for (int o = 16; o > 0; o >>= 1) {
                    hiA = fmaxf(hiA, __shfl_xor_sync(0xffffffffu, hiA, o));
                    hiB = fmaxf(hiB, __shfl_xor_sync(0xffffffffu, hiB, o));
                }
                if (lane == 0) { maxshA[w] = hiA; maxshB[w] = hiB; }
            }
            __syncthreads();
        }
    }

    // end scores: s = sum_t v[t] * exp(T[END,t])  (pending max: no fixup)
    {
        const float eEnd = __expf(__ldg(transition + END_TAG * NTAG + t));
        float sA = vA * eEnd, sB = vB * eEnd;
#pragma unroll
        for (int o = 16; o > 0; o >>= 1) {
            sA += __shfl_xor_sync(0xffffffffu, sA, o);
            sB += __shfl_xor_sync(0xffffffffu, sB, o);
        }
        if (lane == 0) { redA[w] = sA; redB[w] = sB; }
    }

    // ---- realpath: warp w handles batch (bA + w); lanes split L (16 each) --
    {
        const int b = bA + w;
        float rsum = 0.0f, rlen = 0.0f;
#pragma unroll
        for (int i = 0; i < 16; ++i) {
            const int l = lane + 32 * i;
            int tag  = __ldg(tags + l * BSZ + b);
            int prev = (l == 0) ? START_TAG : __ldg(tags + (l - 1) * BSZ + b);
            float m  = __ldg(mask + l * BSZ + b);
            float emit = __ldg(feats + ((size_t)l * BSZ + b) * NTAG + tag);
            float tr   = __ldg(transition + tag * NTAG + prev);
            rsum += (emit + tr) * m;
            rlen += m;
        }
#pragma unroll
        for (int o = 16; o > 0; o >>= 1) {
            rsum += __shfl_xor_sync(0xffffffffu, rsum, o);
            rlen += __shfl_xor_sync(0xffffffffu, rlen, o);
        }
        if (lane == 0) { redr[w] = rsum; redl[w] = rlen; }
    }
    __syncthreads();

    if (tid < 2) {   // thread 0 -> batch A, thread 1 -> batch B
        const int b = bA + tid;
        const float allpath = (tid == 0 ? cA + __logf(redA[0] + redA[1])
                                        : cB + __logf(redB[0] + redB[1]));
        const int length = (int)(redl[tid] + 0.5f);
        const int last = (length > 0) ? __ldg(tags + (length - 1) * BSZ + b)
                                      : START_TAG;
        const float real = redr[tid] + __ldg(transition + END_TAG * NTAG + last);
        out[b] = allpath - real;
    }
}

extern "C" void kernel_launch(void* const* d_in, const int* in_sizes, int n_in,
                              void* d_out, int out_size) {
    const float* feats      = (const float*)d_in[0];
    const int*   tags       = (const int*)  d_in[1];
    const float* mask       = (const float*)d_in[2];
    const float* transition = (const float*)d_in[3];
    float* out = (float*)d_out;

    crf_fused_kernel<<<BSZ / 2, 64>>>(feats, tags, mask, transition, out);
}